// round 3
// baseline (speedup 1.0000x reference)
#include <cuda_runtime.h>

#define NN 65536      // nodes
#define NB 128        // graphs
#define NE 65536      // raw directed edges
#define E2 131072     // TD + BU
#define ETOT 196608   // + self loops
#define DIN 512

// ------------------------- scratch (device globals; no allocs) ---------------
__device__ float g_h1 [NN * 128];   // PLA1 output
__device__ float g_hf [NN * 256];   // GAT lin output (reused layer1 & layer2)
__device__ float g_xr [NN * 256];   // relu(GAT1 out)
__device__ float g_x3 [NN * 512];   // PLA2 output
__device__ float g_xr2[NN * 64];    // relu(GAT2 out)
__device__ float g_asrc[NN * 4];
__device__ float g_adst[NN * 4];
__device__ float g_hc1[NB * 64];
__device__ float g_hc2[NB * 64];
__device__ float g_gsum[NB * 128];  // [s_hat_sum | s_sum] per graph
__device__ int   g_deg[NN];
__device__ int   g_rp [NN + 1];
__device__ int   g_cursor[NN];
__device__ int   g_col[ETOT];
__device__ int   g_bsum[64];

// ------------------------- CSR build -----------------------------------------
__global__ void k_deg_init() {
    int i = blockIdx.x * 256 + threadIdx.x;
    g_deg[i] = 1;                      // self loop
}

__global__ void k_deg(const int* __restrict__ ei) {
    int i = blockIdx.x * 256 + threadIdx.x;       // i < E2
    int d = (i < NE) ? ei[NE + i] : ei[i - NE];   // TD: dst row; BU: flipped
    atomicAdd(&g_deg[d], 1);
}

__global__ void k_scan1() {   // 64 blocks x 1024 threads
    __shared__ int wsum[32];
    int tid = threadIdx.x, lane = tid & 31, wid = tid >> 5;
    int i = blockIdx.x * 1024 + tid;
    int v = g_deg[i];
    int x = v;
#pragma unroll
    for (int o = 1; o < 32; o <<= 1) {
        int y = __shfl_up_sync(0xffffffffu, x, o);
        if (lane >= o) x += y;
    }
    if (lane == 31) wsum[wid] = x;
    __syncthreads();
    if (wid == 0) {
        int s = wsum[lane];
#pragma unroll
        for (int o = 1; o < 32; o <<= 1) {
            int y = __shfl_up_sync(0xffffffffu, s, o);
            if (lane >= o) s += y;
        }
        wsum[lane] = s;
    }
    __syncthreads();
    int base = wid ? wsum[wid - 1] : 0;
    g_rp[i] = base + x - v;            // exclusive, pre-block-offset
    if (tid == 1023) g_bsum[blockIdx.x] = wsum[31];
}

__global__ void k_scan2() {   // 1 block x 64
    __shared__ int s[64];
    int t = threadIdx.x;
    s[t] = g_bsum[t];
    __syncthreads();
    if (t == 0) {
        int acc = 0;
        for (int i = 0; i < 64; i++) { int v = s[i]; s[i] = acc; acc += v; }
    }
    __syncthreads();
    g_bsum[t] = s[t];
}

__global__ void k_scan3() {
    int i = blockIdx.x * 256 + threadIdx.x;
    int v = g_rp[i] + g_bsum[i >> 10];
    g_rp[i] = v;
    g_cursor[i] = v;
    if (i == 0) g_rp[NN] = ETOT;
}

__global__ void k_scatter(const int* __restrict__ ei) {
    int i = blockIdx.x * 256 + threadIdx.x;   // i < ETOT
    int s, d;
    if (i < NE)        { s = ei[i];          d = ei[NE + i]; }
    else if (i < E2)   { int e = i - NE; s = ei[NE + e]; d = ei[e]; }
    else               { s = d = i - E2; }
    int pos = atomicAdd(&g_cursor[d], 1);
    g_col[pos] = s;
}

// ------------------------- root projections ----------------------------------
__global__ void k_rootproj(const float* __restrict__ root,
                           const float* __restrict__ Wc1,
                           const float* __restrict__ Wc2) {
    int b = blockIdx.x, c = threadIdx.x;     // 128 x 64
    float a1 = 0.f, a2 = 0.f;
    for (int k = 0; k < DIN; k++) {
        float rv = root[b * DIN + k];
        a1 += rv * Wc1[k * 64 + c];
        a2 += rv * Wc2[k * 64 + c];
    }
    g_hc1[b * 64 + c] = a1;
    g_hc2[b * 64 + c] = a2;
}

// ------------------------- fused GEMMs (128x64 tile, fp32) -------------------
// MODE 0: h_x = x @ W_post1 (K=512) -> gated PLA1 -> g_h1 [N,128]
// MODE 1: g_h1 @ W1 (K=128, N=256) -> g_hf
// MODE 2: g_xr(as [4N,64]) @ W_post2 (K=64) -> gated PLA2 -> g_x3
// MODE 3: g_x3 @ W2 (K=512, N=256) -> g_hf
template <int MODE>
__launch_bounds__(256)
__global__ void k_gemm(const float* __restrict__ Aarg, const float* __restrict__ Bw) {
    constexpr int K   = (MODE == 0 || MODE == 3) ? 512 : (MODE == 1 ? 128 : 64);
    constexpr int LDB = (MODE == 1 || MODE == 3) ? 256 : 64;
    __shared__ __align__(16) float As[16][128];
    __shared__ __align__(16) float Bs[16][64];

    const float* Ap = (MODE == 0) ? Aarg
                    : (MODE == 1) ? (const float*)g_h1
                    : (MODE == 2) ? (const float*)g_xr
                                  : (const float*)g_x3;

    int tid = threadIdx.x;
    int tx = tid & 15, ty = tid >> 4;
    int m0 = blockIdx.y * 128;
    int n0 = blockIdx.x * 64;
    int ar = tid >> 2, ac = (tid & 3) << 2;
    int br = tid >> 4, bc = (tid & 15) << 2;
    const float* Aptr = Ap + (size_t)(m0 + ar) * K + ac;
    const float* Bptr = Bw + (size_t)br * LDB + n0 + bc;

    float acc[8][4];
#pragma unroll
    for (int i = 0; i < 8; i++)
#pragma unroll
        for (int j = 0; j < 4; j++) acc[i][j] = 0.f;

    for (int k0 = 0; k0 < K; k0 += 16) {
        float4 a0 = *(const float4*)(Aptr + k0);
        float4 a1 = *(const float4*)(Aptr + (size_t)64 * K + k0);
        float4 b0 = *(const float4*)(Bptr + (size_t)k0 * LDB);
        __syncthreads();
        As[ac + 0][ar] = a0.x; As[ac + 1][ar] = a0.y;
        As[ac + 2][ar] = a0.z; As[ac + 3][ar] = a0.w;
        As[ac + 0][ar + 64] = a1.x; As[ac + 1][ar + 64] = a1.y;
        As[ac + 2][ar + 64] = a1.z; As[ac + 3][ar + 64] = a1.w;
        *(float4*)&Bs[br][bc] = b0;
        __syncthreads();
#pragma unroll
        for (int kk = 0; kk < 16; kk++) {
            float4 av0 = *(const float4*)&As[kk][ty * 8];
            float4 av1 = *(const float4*)&As[kk][ty * 8 + 4];
            float4 bv  = *(const float4*)&Bs[kk][tx * 4];
            float a[8] = {av0.x, av0.y, av0.z, av0.w, av1.x, av1.y, av1.z, av1.w};
            float b[4] = {bv.x, bv.y, bv.z, bv.w};
#pragma unroll
            for (int i = 0; i < 8; i++)
#pragma unroll
                for (int j = 0; j < 4; j++) acc[i][j] += a[i] * b[j];
        }
    }

#pragma unroll
    for (int i = 0; i < 8; i++) {
        int row = m0 + ty * 8 + i;
#pragma unroll
        for (int j = 0; j < 4; j++) {
            int c = n0 + tx * 4 + j;
            float v = acc[i][j];
            if (MODE == 1 || MODE == 3) {
                g_hf[(size_t)row * 256 + c] = v;
            } else {
                const float* hcp = (MODE == 0) ? g_hc1 : g_hc2;
                int gid = row >> ((MODE == 0) ? 9 : 11);
                float hc = hcp[gid * 64 + c];
                float gs = 1.f / (1.f + __expf(-(v + hc)));
                float* Cp = (MODE == 0) ? g_h1 : g_x3;
                Cp[(size_t)row * 128 + c]      = gs * v + (1.f - gs) * hc;
                Cp[(size_t)row * 128 + 64 + c] = v;
            }
        }
    }
}

// ------------------------- attention scores ----------------------------------
__launch_bounds__(256)
__global__ void k_scores(const float* __restrict__ as_, const float* __restrict__ ad_) {
    int gw = (blockIdx.x * 256 + threadIdx.x) >> 5;   // node
    int lane = threadIdx.x & 31;
    const float* hr = g_hf + (size_t)gw * 256;
    float ps[4] = {0, 0, 0, 0}, pd[4] = {0, 0, 0, 0};
#pragma unroll
    for (int k = 0; k < 8; k++) {
        int c = lane + 32 * k;
        float v = hr[c];
        ps[k >> 1] += v * as_[c];
        pd[k >> 1] += v * ad_[c];
    }
#pragma unroll
    for (int h = 0; h < 4; h++)
#pragma unroll
        for (int o = 16; o; o >>= 1) {
            ps[h] += __shfl_xor_sync(0xffffffffu, ps[h], o);
            pd[h] += __shfl_xor_sync(0xffffffffu, pd[h], o);
        }
    if (lane == 0) {
#pragma unroll
        for (int h = 0; h < 4; h++) {
            g_asrc[gw * 4 + h] = ps[h];
            g_adst[gw * 4 + h] = pd[h];
        }
    }
}

// ------------------------- GAT aggregation (warp per dst) --------------------
__device__ __forceinline__ float lrelu(float x) { return x > 0.f ? x : 0.2f * x; }

template <int CONCAT>
__launch_bounds__(256)
__global__ void k_agg(const float* __restrict__ bias) {
    int n = (blockIdx.x * 256 + threadIdx.x) >> 5;
    int lane = threadIdx.x & 31;
    int rs = g_rp[n], re = g_rp[n + 1];
    float ad0 = g_adst[n * 4 + 0], ad1 = g_adst[n * 4 + 1];
    float ad2 = g_adst[n * 4 + 2], ad3 = g_adst[n * 4 + 3];

    float m0 = -1e30f, m1 = -1e30f, m2 = -1e30f, m3 = -1e30f;
    for (int j = rs + lane; j < re; j += 32) {
        int s = g_col[j];
        m0 = fmaxf(m0, lrelu(g_asrc[s * 4 + 0] + ad0));
        m1 = fmaxf(m1, lrelu(g_asrc[s * 4 + 1] + ad1));
        m2 = fmaxf(m2, lrelu(g_asrc[s * 4 + 2] + ad2));
        m3 = fmaxf(m3, lrelu(g_asrc[s * 4 + 3] + ad3));
    }
#pragma unroll
    for (int o = 16; o; o >>= 1) {
        m0 = fmaxf(m0, __shfl_xor_sync(0xffffffffu, m0, o));
        m1 = fmaxf(m1, __shfl_xor_sync(0xffffffffu, m1, o));
        m2 = fmaxf(m2, __shfl_xor_sync(0xffffffffu, m2, o));
        m3 = fmaxf(m3, __shfl_xor_sync(0xffffffffu, m3, o));
    }
    float d0 = 0.f, d1 = 0.f, d2 = 0.f, d3 = 0.f;
    for (int j = rs + lane; j < re; j += 32) {
        int s = g_col[j];
        d0 += __expf(lrelu(g_asrc[s * 4 + 0] + ad0) - m0);
        d1 += __expf(lrelu(g_asrc[s * 4 + 1] + ad1) - m1);
        d2 += __expf(lrelu(g_asrc[s * 4 + 2] + ad2) - m2);
        d3 += __expf(lrelu(g_asrc[s * 4 + 3] + ad3) - m3);
    }
#pragma unroll
    for (int o = 16; o; o >>= 1) {
        d0 += __shfl_xor_sync(0xffffffffu, d0, o);
        d1 += __shfl_xor_sync(0xffffffffu, d1, o);
        d2 += __shfl_xor_sync(0xffffffffu, d2, o);
        d3 += __shfl_xor_sync(0xffffffffu, d3, o);
    }
    float i0 = 1.f / d0, i1 = 1.f / d1, i2 = 1.f / d2, i3 = 1.f / d3;

    float acc[8] = {0, 0, 0, 0, 0, 0, 0, 0};
    for (int j = rs; j < re; j++) {
        int s = g_col[j];
        float w0 = __expf(lrelu(g_asrc[s * 4 + 0] + ad0) - m0) * i0;
        float w1 = __expf(lrelu(g_asrc[s * 4 + 1] + ad1) - m1) * i1;
        float w2 = __expf(lrelu(g_asrc[s * 4 + 2] + ad2) - m2) * i2;
        float w3 = __expf(lrelu(g_asrc[s * 4 + 3] + ad3) - m3) * i3;
        const float* hr = g_hf + (size_t)s * 256;
        acc[0] += w0 * hr[lane];       acc[1] += w0 * hr[lane + 32];
        acc[2] += w1 * hr[lane + 64];  acc[3] += w1 * hr[lane + 96];
        acc[4] += w2 * hr[lane + 128]; acc[5] += w2 * hr[lane + 160];
        acc[6] += w3 * hr[lane + 192]; acc[7] += w3 * hr[lane + 224];
    }
    if (CONCAT) {
#pragma unroll
        for (int k = 0; k < 8; k++) {
            int c = lane + 32 * k;
            g_xr[(size_t)n * 256 + c] = fmaxf(acc[k] + bias[c], 0.f);
        }
    } else {
        float o0 = 0.25f * (acc[0] + acc[2] + acc[4] + acc[6]) + bias[lane];
        float o1 = 0.25f * (acc[1] + acc[3] + acc[5] + acc[7]) + bias[lane + 32];
        g_xr2[(size_t)n * 64 + lane]      = fmaxf(o0, 0.f);
        g_xr2[(size_t)n * 64 + lane + 32] = fmaxf(o1, 0.f);
    }
}

// ------------------------- scorer head + pooling -----------------------------
__global__ void k_zero() {
    int i = blockIdx.x * 256 + threadIdx.x;
    g_gsum[i] = 0.f;
}

__launch_bounds__(256)
__global__ void k_final(const float* __restrict__ Wfc, const float* __restrict__ bfc) {
    extern __shared__ float Ws[];           // 16384 floats (W_fc [256][64])
    __shared__ float s_hc3[64];
    __shared__ float part_sh[8][64];
    __shared__ float part_ss[8][64];
    int tid = threadIdx.x, lane = tid & 31, w = tid >> 5;
    int g = blockIdx.x >> 1;

    for (int i = tid; i < 4096; i += 256)
        ((float4*)Ws)[i] = ((const float4*)Wfc)[i];
    if (tid < 64) s_hc3[tid] = g_xr2[((size_t)g << 9) * 64 + tid];
    __syncthreads();

    float bL = bfc[lane], bH = bfc[lane + 32];
    float shL = 0.f, shH = 0.f, ssL = 0.f, ssH = 0.f;
    int nbase = blockIdx.x * 256 + w * 32;

    for (int g4 = 0; g4 < 8; g4++) {
        int n0 = nbase + g4 * 4;
        float xl[4], xh[4], aL[4], aH[4];
#pragma unroll
        for (int u = 0; u < 4; u++) {
            xl[u] = g_xr2[(size_t)(n0 + u) * 64 + lane];
            xh[u] = g_xr2[(size_t)(n0 + u) * 64 + lane + 32];
            aL[u] = bL; aH[u] = bH;
        }
#pragma unroll 4
        for (int j = 0; j < 64; j++) {
            float h3 = s_hc3[j];
            float w0 = Ws[j * 64 + lane];
            float w1 = Ws[(64 + j) * 64 + lane];
            float w2 = Ws[(128 + j) * 64 + lane];
            float w3 = Ws[(192 + j) * 64 + lane];
            float v0 = Ws[j * 64 + lane + 32];
            float v1 = Ws[(64 + j) * 64 + lane + 32];
            float v2 = Ws[(128 + j) * 64 + lane + 32];
            float v3 = Ws[(192 + j) * 64 + lane + 32];
#pragma unroll
            for (int u = 0; u < 4; u++) {
                float xj = (j < 32) ? __shfl_sync(0xffffffffu, xl[u], j)
                                    : __shfl_sync(0xffffffffu, xh[u], j - 32);
                float p = xj * h3;
                float q = fabsf(h3 - xj);
                aL[u] += h3 * w0 + xj * w1 + p * w2 + q * w3;
                aH[u] += h3 * v0 + xj * v1 + p * v2 + q * v3;
            }
        }
#pragma unroll
        for (int u = 0; u < 4; u++) {
            float tL = tanhf(aL[u]), tH = tanhf(aH[u]);
            float mx = fmaxf(tL, tH);
#pragma unroll
            for (int o = 16; o; o >>= 1) mx = fmaxf(mx, __shfl_xor_sync(0xffffffffu, mx, o));
            float eL = __expf(tL - mx), eH = __expf(tH - mx);
            float sm = eL + eH;
#pragma unroll
            for (int o = 16; o; o >>= 1) sm += __shfl_xor_sync(0xffffffffu, sm, o);
            float inv = 1.f / sm;
            shL += eL * inv * xl[u]; shH += eH * inv * xh[u];
            ssL += xl[u];            ssH += xh[u];
        }
    }
    part_sh[w][lane] = shL; part_sh[w][lane + 32] = shH;
    part_ss[w][lane] = ssL; part_ss[w][lane + 32] = ssH;
    __syncthreads();
    if (tid < 128) {
        int c = tid & 63;
        float s = 0.f;
        if (tid < 64) {
            for (int ww = 0; ww < 8; ww++) s += part_sh[ww][c];
            atomicAdd(&g_gsum[g * 128 + c], s);
        } else {
            for (int ww = 0; ww < 8; ww++) s += part_ss[ww][c];
            atomicAdd(&g_gsum[g * 128 + 64 + c], s);
        }
    }
}

__global__ void k_logits(const float* __restrict__ Wc, const float* __restrict__ bc,
                         float* __restrict__ out) {
    int b = threadIdx.x;   // 128
    float l[4] = {bc[0], bc[1], bc[2], bc[3]};
    const float inv = 1.f / 512.f;
    for (int j = 0; j < 128; j++) {
        float v = g_gsum[b * 128 + j] * inv;
#pragma unroll
        for (int c = 0; c < 4; c++) l[c] += v * Wc[j * 4 + c];
    }
    float mx = fmaxf(fmaxf(l[0], l[1]), fmaxf(l[2], l[3]));
    float s = expf(l[0] - mx) + expf(l[1] - mx) + expf(l[2] - mx) + expf(l[3] - mx);
    float lse = mx + logf(s);
#pragma unroll
    for (int c = 0; c < 4; c++) out[b * 4 + c] = l[c] - lse;
}

// ------------------------- launch --------------------------------------------
extern "C" void kernel_launch(void* const* d_in, const int* in_sizes, int n_in,
                              void* d_out, int out_size) {
    const float* x        = (const float*)d_in[0];
    const float* root     = (const float*)d_in[1];
    const int*   ei       = (const int*)d_in[2];
    const float* W_post1  = (const float*)d_in[5];
    const float* W_claim1 = (const float*)d_in[6];
    const float* W1       = (const float*)d_in[7];
    const float* att_src1 = (const float*)d_in[8];
    const float* att_dst1 = (const float*)d_in[9];
    const float* b1       = (const float*)d_in[10];
    const float* W_post2  = (const float*)d_in[11];
    const float* W_claim2 = (const float*)d_in[12];
    const float* W2       = (const float*)d_in[13];
    const float* att_src2 = (const float*)d_in[14];
    const float* att_dst2 = (const float*)d_in[15];
    const float* b2       = (const float*)d_in[16];
    const float* W_fc     = (const float*)d_in[17];
    const float* b_fc     = (const float*)d_in[18];
    const float* W_clf    = (const float*)d_in[19];
    const float* b_clf    = (const float*)d_in[20];
    float* out = (float*)d_out;

    cudaFuncSetAttribute(k_final, cudaFuncAttributeMaxDynamicSharedMemorySize, 65536);

    // CSR build (same every call; atomic ordering only perturbs fp rounding)
    k_deg_init<<<NN / 256, 256>>>();
    k_deg<<<E2 / 256, 256>>>(ei);
    k_scan1<<<64, 1024>>>();
    k_scan2<<<1, 64>>>();
    k_scan3<<<NN / 256, 256>>>();
    k_scatter<<<ETOT / 256, 256>>>(ei);

    k_rootproj<<<NB, 64>>>(root, W_claim1, W_claim2);

    // PLA1 (fused sigmoid gate)
    k_gemm<0><<<dim3(1, NN / 128), 256>>>(x, W_post1);
    // GAT1 linear
    k_gemm<1><<<dim3(4, NN / 128), 256>>>(nullptr, W1);
    k_scores<<<NN * 32 / 256, 256>>>(att_src1, att_dst1);
    k_agg<1><<<NN * 32 / 256, 256>>>(b1);
    // PLA2 (block-diagonal, fused gate)
    k_gemm<2><<<dim3(1, NN * 4 / 128), 256>>>(nullptr, W_post2);
    // GAT2 linear
    k_gemm<3><<<dim3(4, NN / 128), 256>>>(nullptr, W2);
    k_scores<<<NN * 32 / 256, 256>>>(att_src2, att_dst2);
    k_agg<0><<<NN * 32 / 256, 256>>>(b2);

    // scorer head + pooling + classifier
    k_zero<<<NB * 128 / 256, 256>>>();
    k_final<<<NN / 256, 256, 65536>>>(W_fc, b_fc);
    k_logits<<<1, 128>>>(W_clf, b_clf, out);
}

// round 5
// speedup vs baseline: 1.2442x; 1.2442x over previous
#include <cuda_runtime.h>
#include <cuda_bf16.h>
#include <cstdint>

#define NN 65536      // nodes
#define NB 128        // graphs
#define NE 65536      // raw directed edges
#define E2 131072     // TD + BU
#define ETOT 196608   // + self loops
#define DIN 512

// ------------------------- scratch (device globals; no allocs) ---------------
__device__ float g_h1 [NN * 128];   // PLA1 output
__device__ float g_hf [NN * 256];   // GAT lin output (reused layer1 & layer2)
__device__ float g_xr [NN * 256];   // relu(GAT1 out)
__device__ float g_x3 [NN * 512];   // PLA2 output
__device__ float g_xr2[NN * 64];    // relu(GAT2 out)
__device__ float g_asrc[NN * 4];
__device__ float g_adst[NN * 4];
__device__ float g_hc1[NB * 64];
__device__ float g_hc2[NB * 64];
__device__ float g_gsum[NB * 128];
__device__ int   g_deg[NN];
__device__ int   g_rp [NN + 1];
__device__ int   g_cursor[NN];
__device__ int   g_col[ETOT];
__device__ int   g_bsum[64];

// ------------------------- helpers -------------------------------------------
__device__ __forceinline__ uint32_t smem_u32(const void* p) {
    uint32_t a;
    asm("{ .reg .u64 t; cvta.to.shared.u64 t, %1; cvt.u32.u64 %0, t; }" : "=r"(a) : "l"(p));
    return a;
}
__device__ __forceinline__ void ldmat4(uint32_t& r0, uint32_t& r1, uint32_t& r2,
                                       uint32_t& r3, uint32_t addr) {
    asm volatile("ldmatrix.sync.aligned.m8n8.x4.shared.b16 {%0,%1,%2,%3}, [%4];"
        : "=r"(r0), "=r"(r1), "=r"(r2), "=r"(r3) : "r"(addr));
}
__device__ __forceinline__ void ldmat2(uint32_t& r0, uint32_t& r1, uint32_t addr) {
    asm volatile("ldmatrix.sync.aligned.m8n8.x2.shared.b16 {%0,%1}, [%2];"
        : "=r"(r0), "=r"(r1) : "r"(addr));
}
__device__ __forceinline__ void mma_bf16(float* c, const uint32_t* a, const uint32_t* b) {
    asm volatile("mma.sync.aligned.m16n8k16.row.col.f32.bf16.bf16.f32 "
        "{%0,%1,%2,%3}, {%4,%5,%6,%7}, {%8,%9}, {%0,%1,%2,%3};"
        : "+f"(c[0]), "+f"(c[1]), "+f"(c[2]), "+f"(c[3])
        : "r"(a[0]), "r"(a[1]), "r"(a[2]), "r"(a[3]), "r"(b[0]), "r"(b[1]));
}
__device__ __forceinline__ uint32_t pack_hi(float a, float b) {
    __nv_bfloat162 t = __floats2bfloat162_rn(a, b);
    return *reinterpret_cast<uint32_t*>(&t);
}
__device__ __forceinline__ uint32_t pack_lo(float a, float b) {
    float ra = a - __bfloat162float(__float2bfloat16(a));
    float rb = b - __bfloat162float(__float2bfloat16(b));
    __nv_bfloat162 t = __floats2bfloat162_rn(ra, rb);
    return *reinterpret_cast<uint32_t*>(&t);
}

// ------------------------- CSR build -----------------------------------------
__global__ void k_deg_init() { g_deg[blockIdx.x * 256 + threadIdx.x] = 1; }

__global__ void k_deg(const int* __restrict__ ei) {
    int i = blockIdx.x * 256 + threadIdx.x;
    int d = (i < NE) ? ei[NE + i] : ei[i - NE];
    atomicAdd(&g_deg[d], 1);
}

__global__ void k_scan1() {
    __shared__ int wsum[32];
    int tid = threadIdx.x, lane = tid & 31, wid = tid >> 5;
    int i = blockIdx.x * 1024 + tid;
    int v = g_deg[i];
    int x = v;
#pragma unroll
    for (int o = 1; o < 32; o <<= 1) {
        int y = __shfl_up_sync(0xffffffffu, x, o);
        if (lane >= o) x += y;
    }
    if (lane == 31) wsum[wid] = x;
    __syncthreads();
    if (wid == 0) {
        int s = wsum[lane];
#pragma unroll
        for (int o = 1; o < 32; o <<= 1) {
            int y = __shfl_up_sync(0xffffffffu, s, o);
            if (lane >= o) s += y;
        }
        wsum[lane] = s;
    }
    __syncthreads();
    int base = wid ? wsum[wid - 1] : 0;
    g_rp[i] = base + x - v;
    if (tid == 1023) g_bsum[blockIdx.x] = wsum[31];
}

__global__ void k_scan2() {
    __shared__ int s[64];
    int t = threadIdx.x;
    s[t] = g_bsum[t];
    __syncthreads();
    if (t == 0) {
        int acc = 0;
        for (int i = 0; i < 64; i++) { int v = s[i]; s[i] = acc; acc += v; }
    }
    __syncthreads();
    g_bsum[t] = s[t];
}

__global__ void k_scan3() {
    int i = blockIdx.x * 256 + threadIdx.x;
    int v = g_rp[i] + g_bsum[i >> 10];
    g_rp[i] = v;
    g_cursor[i] = v;
    if (i == 0) g_rp[NN] = ETOT;
}

__global__ void k_scatter(const int* __restrict__ ei) {
    int i = blockIdx.x * 256 + threadIdx.x;
    int s, d;
    if (i < NE)        { s = ei[i];          d = ei[NE + i]; }
    else if (i < E2)   { int e = i - NE; s = ei[NE + e]; d = ei[e]; }
    else               { s = d = i - E2; }
    int pos = atomicAdd(&g_cursor[d], 1);
    g_col[pos] = s;
}

// ------------------------- root projections ----------------------------------
__global__ void k_rootproj(const float* __restrict__ root,
                           const float* __restrict__ Wc1,
                           const float* __restrict__ Wc2) {
    int b = blockIdx.x, c = threadIdx.x;
    float a1 = 0.f, a2 = 0.f;
    for (int k = 0; k < DIN; k++) {
        float rv = root[b * DIN + k];
        a1 += rv * Wc1[k * 64 + c];
        a2 += rv * Wc2[k * 64 + c];
    }
    g_hc1[b * 64 + c] = a1;
    g_hc2[b * 64 + c] = a2;
}

// ------------------------- split-bf16 mma.sync GEMM --------------------------
// MODE 0: x    @ W_post1 [512->64]  -> PLA1 gate -> g_h1  (M=65536)
// MODE 1: g_h1 @ W1      [128->256] -> g_hf              (M=65536)
// MODE 2: g_xr @ W_post2 [64->64]   -> PLA2 gate -> g_x3 (M=262144 head-rows)
// MODE 3: g_x3 @ W2      [512->256] -> g_hf              (M=65536)
// Block tile 128x64, warp tile 64x16 (2x4 warps), K staged 64/iter in smem,
// 3-pass split-bf16 (hi*hi + hi*lo + lo*hi) with fp32 register accumulators.
#define LDS 72            // padded smem row stride (bf16 elems): 144B

template <int MODE>
__launch_bounds__(256, 2)
__global__ void k_mm(const float* __restrict__ Aarg, const float* __restrict__ Bw) {
    constexpr int K   = (MODE == 0 || MODE == 3) ? 512 : (MODE == 1 ? 128 : 64);
    constexpr int LDB = (MODE == 1 || MODE == 3) ? 256 : 64;

    extern __shared__ __align__(16) char sm[];
    __nv_bfloat16* Ah = (__nv_bfloat16*)sm;     // [128][LDS]
    __nv_bfloat16* Al = Ah + 128 * LDS;
    __nv_bfloat16* Bh = Al + 128 * LDS;         // [64][LDS] (n-major = B col-major)
    __nv_bfloat16* Bl = Bh + 64 * LDS;

    int tid = threadIdx.x, lane = tid & 31, w = tid >> 5;
    int wm = (w & 1) * 64, wn = (w >> 1) * 16;

    const float* Ap = (MODE == 0) ? Aarg
                    : (MODE == 1) ? (const float*)g_h1
                    : (MODE == 2) ? (const float*)g_xr
                                  : (const float*)g_x3;
    const float* Arow = Ap + (size_t)blockIdx.y * 128 * K;
    int n0 = blockIdx.x * 64;

    float acc[4][2][4];
#pragma unroll
    for (int a = 0; a < 4; a++)
#pragma unroll
        for (int b = 0; b < 2; b++)
#pragma unroll
            for (int c = 0; c < 4; c++) acc[a][b][c] = 0.f;

    for (int k0 = 0; k0 < K; k0 += 64) {
        if (k0) __syncthreads();
        // --- A stage: 128 rows x 64 k, fp32 -> hi/lo bf16 ---
#pragma unroll
        for (int i = 0; i < 8; i++) {
            int idx = i * 256 + tid;              // 2048 float4s
            int r = idx >> 4, c4 = (idx & 15) << 2;
            float4 v = *(const float4*)(Arow + (size_t)r * K + k0 + c4);
            *(uint2*)&Ah[r * LDS + c4] = make_uint2(pack_hi(v.x, v.y), pack_hi(v.z, v.w));
            *(uint2*)&Al[r * LDS + c4] = make_uint2(pack_lo(v.x, v.y), pack_lo(v.z, v.w));
        }
        // --- B stage: 64 k x 64 n from W[k][n] -> smem [n][k] ---
#pragma unroll
        for (int i = 0; i < 4; i++) {
            int idx = i * 256 + tid;              // 1024 float4s
            int kk = idx >> 4, n4 = (idx & 15) << 2;
            float4 v = *(const float4*)(Bw + (size_t)(k0 + kk) * LDB + n0 + n4);
            float e[4] = {v.x, v.y, v.z, v.w};
#pragma unroll
            for (int j = 0; j < 4; j++) {
                __nv_bfloat16 h = __float2bfloat16(e[j]);
                Bh[(n4 + j) * LDS + kk] = h;
                Bl[(n4 + j) * LDS + kk] = __float2bfloat16(e[j] - __bfloat162float(h));
            }
        }
        __syncthreads();

#pragma unroll
        for (int ks = 0; ks < 4; ks++) {
            int kb = ks * 16;
            uint32_t ah[4][4], al[4][4], bh[2][2], bl[2][2];
            int arow = wm + (lane & 15);
            int acol = kb + (lane >> 4) * 8;
#pragma unroll
            for (int mf = 0; mf < 4; mf++) {
                ldmat4(ah[mf][0], ah[mf][1], ah[mf][2], ah[mf][3],
                       smem_u32(&Ah[(arow + mf * 16) * LDS + acol]));
                ldmat4(al[mf][0], al[mf][1], al[mf][2], al[mf][3],
                       smem_u32(&Al[(arow + mf * 16) * LDS + acol]));
            }
            int brow = wn + (lane & 7);
            int bcol = kb + ((lane >> 3) & 1) * 8;
#pragma unroll
            for (int nf = 0; nf < 2; nf++) {
                ldmat2(bh[nf][0], bh[nf][1], smem_u32(&Bh[(brow + nf * 8) * LDS + bcol]));
                ldmat2(bl[nf][0], bl[nf][1], smem_u32(&Bl[(brow + nf * 8) * LDS + bcol]));
            }
#pragma unroll
            for (int mf = 0; mf < 4; mf++)
#pragma unroll
                for (int nf = 0; nf < 2; nf++) {
                    mma_bf16(acc[mf][nf], ah[mf], bh[nf]);
                    mma_bf16(acc[mf][nf], ah[mf], bl[nf]);
                    mma_bf16(acc[mf][nf], al[mf], bh[nf]);
                }
        }
    }

    // --- epilogue from register accumulators ---
#pragma unroll
    for (int mf = 0; mf < 4; mf++)
#pragma unroll
        for (int nf = 0; nf < 2; nf++)
#pragma unroll
            for (int p = 0; p < 2; p++) {
                int row = blockIdx.y * 128 + wm + mf * 16 + (lane >> 2) + p * 8;
                int c   = wn + nf * 8 + (lane & 3) * 2;
                float v0 = acc[mf][nf][p * 2 + 0];
                float v1 = acc[mf][nf][p * 2 + 1];
                if (MODE == 1 || MODE == 3) {
                    g_hf[(size_t)row * 256 + n0 + c]     = v0;
                    g_hf[(size_t)row * 256 + n0 + c + 1] = v1;
                } else {
                    const float* hcp = (MODE == 0) ? g_hc1 : g_hc2;
                    int gid = row >> ((MODE == 0) ? 9 : 11);
                    float* Cp = (MODE == 0) ? g_h1 : g_x3;
                    float hc0 = hcp[gid * 64 + c];
                    float hc1 = hcp[gid * 64 + c + 1];
                    float gs0 = 1.f / (1.f + __expf(-(v0 + hc0)));
                    float gs1 = 1.f / (1.f + __expf(-(v1 + hc1)));
                    Cp[(size_t)row * 128 + c]          = gs0 * v0 + (1.f - gs0) * hc0;
                    Cp[(size_t)row * 128 + c + 1]      = gs1 * v1 + (1.f - gs1) * hc1;
                    Cp[(size_t)row * 128 + 64 + c]     = v0;
                    Cp[(size_t)row * 128 + 64 + c + 1] = v1;
                }
            }
}

// ------------------------- attention scores ----------------------------------
__launch_bounds__(256)
__global__ void k_scores(const float* __restrict__ as_, const float* __restrict__ ad_) {
    int gw = (blockIdx.x * 256 + threadIdx.x) >> 5;
    int lane = threadIdx.x & 31;
    const float* hr = g_hf + (size_t)gw * 256;
    float ps[4] = {0, 0, 0, 0}, pd[4] = {0, 0, 0, 0};
#pragma unroll
    for (int k = 0; k < 8; k++) {
        int c = lane + 32 * k;
        float v = hr[c];
        ps[k >> 1] += v * as_[c];
        pd[k >> 1] += v * ad_[c];
    }
#pragma unroll
    for (int h = 0; h < 4; h++)
#pragma unroll
        for (int o = 16; o; o >>= 1) {
            ps[h] += __shfl_xor_sync(0xffffffffu, ps[h], o);
            pd[h] += __shfl_xor_sync(0xffffffffu, pd[h], o);
        }
    if (lane == 0) {
#pragma unroll
        for (int h = 0; h < 4; h++) {
            g_asrc[gw * 4 + h] = ps[h];
            g_adst[gw * 4 + h] = pd[h];
        }
    }
}

// ------------------------- GAT aggregation (warp per dst) --------------------
__device__ __forceinline__ float lrelu(float x) { return x > 0.f ? x : 0.2f * x; }

template <int CONCAT>
__launch_bounds__(256)
__global__ void k_agg(const float* __restrict__ bias) {
    int n = (blockIdx.x * 256 + threadIdx.x) >> 5;
    int lane = threadIdx.x & 31;
    int rs = g_rp[n], re = g_rp[n + 1];
    float ad0 = g_adst[n * 4 + 0], ad1 = g_adst[n * 4 + 1];
    float ad2 = g_adst[n * 4 + 2], ad3 = g_adst[n * 4 + 3];

    float m0 = -1e30f, m1 = -1e30f, m2 = -1e30f, m3 = -1e30f;
    for (int j = rs + lane; j < re; j += 32) {
        int s = g_col[j];
        m0 = fmaxf(m0, lrelu(g_asrc[s * 4 + 0] + ad0));
        m1 = fmaxf(m1, lrelu(g_asrc[s * 4 + 1] + ad1));
        m2 = fmaxf(m2, lrelu(g_asrc[s * 4 + 2] + ad2));
        m3 = fmaxf(m3, lrelu(g_asrc[s * 4 + 3] + ad3));
    }
#pragma unroll
    for (int o = 16; o; o >>= 1) {
        m0 = fmaxf(m0, __shfl_xor_sync(0xffffffffu, m0, o));
        m1 = fmaxf(m1, __shfl_xor_sync(0xffffffffu, m1, o));
        m2 = fmaxf(m2, __shfl_xor_sync(0xffffffffu, m2, o));
        m3 = fmaxf(m3, __shfl_xor_sync(0xffffffffu, m3, o));
    }
    float d0 = 0.f, d1 = 0.f, d2 = 0.f, d3 = 0.f;
    for (int j = rs + lane; j < re; j += 32) {
        int s = g_col[j];
        d0 += __expf(lrelu(g_asrc[s * 4 + 0] + ad0) - m0);
        d1 += __expf(lrelu(g_asrc[s * 4 + 1] + ad1) - m1);
        d2 += __expf(lrelu(g_asrc[s * 4 + 2] + ad2) - m2);
        d3 += __expf(lrelu(g_asrc[s * 4 + 3] + ad3) - m3);
    }
#pragma unroll
    for (int o = 16; o; o >>= 1) {
        d0 += __shfl_xor_sync(0xffffffffu, d0, o);
        d1 += __shfl_xor_sync(0xffffffffu, d1, o);
        d2 += __shfl_xor_sync(0xffffffffu, d2, o);
        d3 += __shfl_xor_sync(0xffffffffu, d3, o);
    }
    float i0 = 1.f / d0, i1 = 1.f / d1, i2 = 1.f / d2, i3 = 1.f / d3;

    float acc[8] = {0, 0, 0, 0, 0, 0, 0, 0};
    for (int j = rs; j < re; j++) {
        int s = g_col[j];
        float w0 = __expf(lrelu(g_asrc[s * 4 + 0] + ad0) - m0) * i0;
        float w1 = __expf(lrelu(g_asrc[s * 4 + 1] + ad1) - m1) * i1;
        float w2 = __expf(lrelu(g_asrc[s * 4 + 2] + ad2) - m2) * i2;
        float w3 = __expf(lrelu(g_asrc[s * 4 + 3] + ad3) - m3) * i3;
        const float* hr = g_hf + (size_t)s * 256;
        acc[0] += w0 * hr[lane];       acc[1] += w0 * hr[lane + 32];
        acc[2] += w1 * hr[lane + 64];  acc[3] += w1 * hr[lane + 96];
        acc[4] += w2 * hr[lane + 128]; acc[5] += w2 * hr[lane + 160];
        acc[6] += w3 * hr[lane + 192]; acc[7] += w3 * hr[lane + 224];
    }
    if (CONCAT) {
#pragma unroll
        for (int k = 0; k < 8; k++) {
            int c = lane + 32 * k;
            g_xr[(size_t)n * 256 + c] = fmaxf(acc[k] + bias[c], 0.f);
        }
    } else {
        float o0 = 0.25f * (acc[0] + acc[2] + acc[4] + acc[6]) + bias[lane];
        float o1 = 0.25f * (acc[1] + acc[3] + acc[5] + acc[7]) + bias[lane + 32];
        g_xr2[(size_t)n * 64 + lane]      = fmaxf(o0, 0.f);
        g_xr2[(size_t)n * 64 + lane + 32] = fmaxf(o1, 0.f);
    }
}

// ------------------------- scorer head + pooling -----------------------------
__global__ void k_zero() { g_gsum[blockIdx.x * 256 + threadIdx.x] = 0.f; }

__launch_bounds__(256)
__global__ void k_final(const float* __restrict__ Wfc, const float* __restrict__ bfc) {
    extern __shared__ float Ws[];
    __shared__ float s_hc3[64];
    __shared__ float part_sh[8][64];
    __shared__ float part_ss[8][64];
    int tid = threadIdx.x, lane = tid & 31, w = tid >> 5;
    int g = blockIdx.x >> 1;

    for (int i = tid; i < 4096; i += 256)
        ((float4*)Ws)[i] = ((const float4*)Wfc)[i];
    if (tid < 64) s_hc3[tid] = g_xr2[((size_t)g << 9) * 64 + tid];
    __syncthreads();

    float bL = bfc[lane], bH = bfc[lane + 32];
    float shL = 0.f, shH = 0.f, ssL = 0.f, ssH = 0.f;
    int nbase = blockIdx.x * 256 + w * 32;

    for (int g4 = 0; g4 < 8; g4++) {
        int n0 = nbase + g4 * 4;
        float xl[4], xh[4], aL[4], aH[4];
#pragma unroll
        for (int u = 0; u < 4; u++) {
            xl[u] = g_xr2[(size_t)(n0 + u) * 64 + lane];
            xh[u] = g_xr2[(size_t)(n0 + u) * 64 + lane + 32];
            aL[u] = bL; aH[u] = bH;
        }
#pragma unroll 4
        for (int j = 0; j < 64; j++) {
            float h3 = s_hc3[j];
            float w0 = Ws[j * 64 + lane];
            float w1 = Ws[(64 + j) * 64 + lane];
            float w2 = Ws[(128 + j) * 64 + lane];
            float w3 = Ws[(192 + j) * 64 + lane];
            float v0 = Ws[j * 64 + lane + 32];
            float v1 = Ws[(64 + j) * 64 + lane + 32];
            float v2 = Ws[(128 + j) * 64 + lane + 32];
            float v3 = Ws[(192 + j) * 64 + lane + 32];
#pragma unroll
            for (int u = 0; u < 4; u++) {
                float xj = (j < 32) ? __shfl_sync(0xffffffffu, xl[u], j)
                                    : __shfl_sync(0xffffffffu, xh[u], j - 32);
                float p = xj * h3;
                float q = fabsf(h3 - xj);
                aL[u] += h3 * w0 + xj * w1 + p * w2 + q * w3;
                aH[u] += h3 * v0 + xj * v1 + p * v2 + q * v3;
            }
        }
#pragma unroll
        for (int u = 0; u < 4; u++) {
            float tL = tanhf(aL[u]), tH = tanhf(aH[u]);
            float mx = fmaxf(tL, tH);
#pragma unroll
            for (int o = 16; o; o >>= 1) mx = fmaxf(mx, __shfl_xor_sync(0xffffffffu, mx, o));
            float eL = __expf(tL - mx), eH = __expf(tH - mx);
            float sm = eL + eH;
#pragma unroll
            for (int o = 16; o; o >>= 1) sm += __shfl_xor_sync(0xffffffffu, sm, o);
            float inv = 1.f / sm;
            shL += eL * inv * xl[u]; shH += eH * inv * xh[u];
            ssL += xl[u];            ssH += xh[u];
        }
    }
    part_sh[w][lane] = shL; part_sh[w][lane + 32] = shH;
    part_ss[w][lane] = ssL; part_ss[w][lane + 32] = ssH;
    __syncthreads();
    if (tid < 128) {
        int c = tid & 63;
        float s = 0.f;
        if (tid < 64) {
            for (int ww = 0; ww < 8; ww++) s += part_sh[ww][c];
            atomicAdd(&g_gsum[g * 128 + c], s);
        } else {
            for (int ww = 0; ww < 8; ww++) s += part_ss[ww][c];
            atomicAdd(&g_gsum[g * 128 + 64 + c], s);
        }
    }
}

__global__ void k_logits(const float* __restrict__ Wc, const float* __restrict__ bc,
                         float* __restrict__ out) {
    int b = threadIdx.x;
    float l[4] = {bc[0], bc[1], bc[2], bc[3]};
    const float inv = 1.f / 512.f;
    for (int j = 0; j < 128; j++) {
        float v = g_gsum[b * 128 + j] * inv;
#pragma unroll
        for (int c = 0; c < 4; c++) l[c] += v * Wc[j * 4 + c];
    }
    float mx = fmaxf(fmaxf(l[0], l[1]), fmaxf(l[2], l[3]));
    float s = expf(l[0] - mx) + expf(l[1] - mx) + expf(l[2] - mx) + expf(l[3] - mx);
    float lse = mx + logf(s);
#pragma unroll
    for (int c = 0; c < 4; c++) out[b * 4 + c] = l[c] - lse;
}

// ------------------------- launch --------------------------------------------
extern "C" void kernel_launch(void* const* d_in, const int* in_sizes, int n_in,
                              void* d_out, int out_size) {
    const float* x        = (const float*)d_in[0];
    const float* root     = (const float*)d_in[1];
    const int*   ei       = (const int*)d_in[2];
    const float* W_post1  = (const float*)d_in[5];
    const float* W_claim1 = (const float*)d_in[6];
    const float* W1       = (const float*)d_in[7];
    const float* att_src1 = (const float*)d_in[8];
    const float* att_dst1 = (const float*)d_in[9];
    const float* b1       = (const float*)d_in[10];
    const float* W_post2  = (const float*)d_in[11];
    const float* W_claim2 = (const float*)d_in[12];
    const float* W2       = (const float*)d_in[13];
    const float* att_src2 = (const float*)d_in[14];
    const float* att_dst2 = (const float*)d_in[15];
    const float* b2       = (const float*)d_in[16];
    const float* W_fc     = (const float*)d_in[17];
    const float* b_fc     = (const float*)d_in[18];
    const float* W_clf    = (const float*)d_in[19];
    const float* b_clf    = (const float*)d_in[20];
    float* out = (float*)d_out;

    const int SMM = (128 * LDS * 2 + 64 * LDS * 2) * 2;   // 55296 bytes
    cudaFuncSetAttribute(k_final, cudaFuncAttributeMaxDynamicSharedMemorySize, 65536);
    cudaFuncSetAttribute(k_mm<0>, cudaFuncAttributeMaxDynamicSharedMemorySize, SMM);
    cudaFuncSetAttribute(k_mm<1>, cudaFuncAttributeMaxDynamicSharedMemorySize, SMM);
    cudaFuncSetAttribute(k_mm<2>, cudaFuncAttributeMaxDynamicSharedMemorySize, SMM);
    cudaFuncSetAttribute(k_mm<3>, cudaFuncAttributeMaxDynamicSharedMemorySize, SMM);

    // CSR build
    k_deg_init<<<NN / 256, 256>>>();
    k_deg<<<E2 / 256, 256>>>(ei);
    k_scan1<<<64, 1024>>>();
    k_scan2<<<1, 64>>>();
    k_scan3<<<NN / 256, 256>>>();
    k_scatter<<<ETOT / 256, 256>>>(ei);

    k_rootproj<<<NB, 64>>>(root, W_claim1, W_claim2);

    // PLA1 (fused sigmoid gate)
    k_mm<0><<<dim3(1, NN / 128), 256, SMM>>>(x, W_post1);
    // GAT1 linear
    k_mm<1><<<dim3(4, NN / 128), 256, SMM>>>(nullptr, W1);
    k_scores<<<NN * 32 / 256, 256>>>(att_src1, att_dst1);
    k_agg<1><<<NN * 32 / 256, 256>>>(b1);
    // PLA2 (block-diagonal, fused gate)
    k_mm<2><<<dim3(1, NN * 4 / 128), 256, SMM>>>(nullptr, W_post2);
    // GAT2 linear
    k_mm<3><<<dim3(4, NN / 128), 256, SMM>>>(nullptr, W2);
    k_scores<<<NN * 32 / 256, 256>>>(att_src2, att_dst2);
    k_agg<0><<<NN * 32 / 256, 256>>>(b2);

    // scorer head + pooling + classifier
    k_zero<<<NB * 128 / 256, 256>>>();
    k_final<<<NN / 256, 256, 65536>>>(W_fc, b_fc);
    k_logits<<<1, 128>>>(W_clf, b_clf, out);
}